// round 16
// baseline (speedup 1.0000x reference)
#include <cuda_runtime.h>
#include <cuda_fp16.h>
#include <cstdint>

#define B_  8
#define N_  4096
#define M_  2048
#define D_  256
#define DV_ 256
#define INV_T (1.0f / 16.0f)
#define MASK_FILL_H (-60000.0f)   // fp16-representable; exp-equivalent to -1e9

// ---------------------------------------------------------------------------
// Scratch (__device__ globals; no dynamic allocation allowed).
// g_a16 is dual-use: qk writes fp16 masked logits; softmax overwrites with
// fp16 attention weights (read by av). g_a16 keeps DEFAULT cache policy (it
// is the only re-read intermediate); all single-touch traffic uses .cs.
// ---------------------------------------------------------------------------
__device__ __half g_q16[(size_t)B_ * N_ * D_];
__device__ __half g_k16[(size_t)B_ * M_ * D_];
__device__ __half g_vt16[(size_t)B_ * DV_ * M_];   // V^T [B, DV, M]
__device__ __half g_a16[(size_t)B_ * N_ * M_];     // logits -> attn (fp16)

// ---------------------------------------------------------------------------
// Helpers (plain sm_80+ PTX only — tcgen05 is feature-gated off this target).
// ---------------------------------------------------------------------------
__device__ __forceinline__ uint32_t smem_u32(const void* p) {
    uint32_t a;
    asm("{ .reg .u64 t; cvta.to.shared.u64 t, %1; cvt.u32.u64 %0, t; }"
        : "=r"(a) : "l"(p));
    return a;
}

__device__ __forceinline__ void cp16(uint32_t dst, const void* src) {
    asm volatile("cp.async.cg.shared.global [%0], [%1], 16;"
                 :: "r"(dst), "l"(src));
}
#define CP_COMMIT() asm volatile("cp.async.commit_group;" ::: "memory")
#define CP_WAIT(n)  asm volatile("cp.async.wait_group %0;" :: "n"(n) : "memory")

#define LDSM_X4(r0, r1, r2, r3, addr)                                         \
    asm volatile("ldmatrix.sync.aligned.m8n8.x4.shared.b16 {%0,%1,%2,%3}, [%4];" \
                 : "=r"(r0), "=r"(r1), "=r"(r2), "=r"(r3) : "r"(addr))

#define MMA16816(d, a, b)                                                     \
    asm volatile("mma.sync.aligned.m16n8k16.row.col.f32.f16.f16.f32 "         \
                 "{%0,%1,%2,%3}, {%4,%5,%6,%7}, {%8,%9}, {%0,%1,%2,%3};"      \
                 : "+f"((d)[0]), "+f"((d)[1]), "+f"((d)[2]), "+f"((d)[3])     \
                 : "r"((a)[0]), "r"((a)[1]), "r"((a)[2]), "r"((a)[3]),        \
                   "r"((b)[0]), "r"((b)[1]))

// SW64 swizzle for 64-byte rows (32 fp16): conflict-free ldmatrix phases.
__device__ __forceinline__ uint32_t sw64(uint32_t off) {
    return off ^ ((off >> 3) & 0x30);
}

// ---------------------------------------------------------------------------
// Prep kernels. prep_qk converts q (scaled) and k in one launch.
// ---------------------------------------------------------------------------
#define QELEMS ((size_t)B_ * N_ * D_)

__global__ void __launch_bounds__(256) prep_qk_kernel(
    const float* __restrict__ q, const float* __restrict__ k)
{
    size_t i = ((size_t)blockIdx.x * 256 + threadIdx.x) * 4;
    if (i < QELEMS) {
        float4 x = __ldcs((const float4*)(q + i));
        __half2* d = (__half2*)(g_q16 + i);
        d[0] = {__float2half(x.x * INV_T), __float2half(x.y * INV_T)};
        d[1] = {__float2half(x.z * INV_T), __float2half(x.w * INV_T)};
    } else {
        size_t j = i - QELEMS;
        float4 x = __ldcs((const float4*)(k + j));
        __half2* d = (__half2*)(g_k16 + j);
        d[0] = {__float2half(x.x), __float2half(x.y)};
        d[1] = {__float2half(x.z), __float2half(x.w)};
    }
}

__global__ void prep_vt_kernel(const float* __restrict__ v) {
    __shared__ float t[32][33];
    const int b = blockIdx.z, m0 = blockIdx.x * 32, c0 = blockIdx.y * 32;
    for (int j = threadIdx.y; j < 32; j += 8)
        t[j][threadIdx.x] =
            __ldcs(v + ((size_t)b * M_ + m0 + j) * DV_ + c0 + threadIdx.x);
    __syncthreads();
    for (int j = threadIdx.y; j < 32; j += 8) {
        size_t o = ((size_t)b * DV_ + c0 + j) * M_ + m0 + threadIdx.x;
        g_vt16[o] = __float2half(t[threadIdx.x][j]);
    }
}

// ---------------------------------------------------------------------------
// AV mainloop (R11-proven): block 64x128, 8 warps 2x4, warp 32x32,
// K-chunks of 32, 4-stage ring. Stage = A 4KB | B 8KB = 12KB.
// ---------------------------------------------------------------------------
template <int NC>
__device__ __forceinline__ void gemm_mainloop(
    const __half* const* srcs, const size_t sstride,
    uint32_t sb, int tid, int wrow, int wcol, int lane, float acc[2][4][4])
{
    const uint32_t STAGE = 12288u;
    const uint32_t BBASE = 4096u;

    auto load_stage = [&](int c) {
        const uint32_t stg = sb + (uint32_t)(c & 3) * STAGE;
        const int kt = c * 32;
#pragma unroll
        for (int u0 = 0; u0 < 768; u0 += 256) {
            const int u = u0 + tid;
            const int rt = u >> 2, seg = u & 3;
            const __half* src;
            uint32_t base;
            int r;
            if (rt < 64) { src = srcs[0]; base = 0u; r = rt; }
            else         { src = srcs[1]; base = BBASE; r = rt - 64; }
            cp16(stg + base + sw64((uint32_t)(r * 64 + seg * 16)),
                 src + (size_t)r * sstride + kt + seg * 8);
        }
        CP_COMMIT();
    };

    load_stage(0);
    if (NC > 1) load_stage(1);
    if (NC > 2) load_stage(2);

    for (int c = 0; c < NC; c++) {
        if (c + 3 <= NC) { CP_WAIT(2); }
        else if (c + 2 == NC) { CP_WAIT(1); }
        else { CP_WAIT(0); }
        __syncthreads();

        const uint32_t stg = sb + (uint32_t)(c & 3) * STAGE;
#pragma unroll
        for (int kk = 0; kk < 2; kk++) {
            uint32_t af[2][4], bf[4][2];
#pragma unroll
            for (int i = 0; i < 2; i++) {
                uint32_t off = (uint32_t)((wrow * 32 + i * 16 + (lane & 15)) * 64
                                          + ((lane >> 4) * 16) + kk * 32);
                LDSM_X4(af[i][0], af[i][1], af[i][2], af[i][3], stg + sw64(off));
            }
#pragma unroll
            for (int jj = 0; jj < 2; jj++) {
                uint32_t off = (uint32_t)((wcol * 32 + jj * 16 + (lane & 15)) * 64
                                          + ((lane >> 4) * 16) + kk * 32);
                uint32_t r0, r1, r2, r3;
                LDSM_X4(r0, r1, r2, r3, stg + BBASE + sw64(off));
                bf[jj * 2][0] = r0; bf[jj * 2][1] = r2;
                bf[jj * 2 + 1][0] = r1; bf[jj * 2 + 1][1] = r3;
            }
#pragma unroll
            for (int i = 0; i < 2; i++)
#pragma unroll
                for (int j = 0; j < 4; j++)
                    MMA16816(acc[i][j], af[i], bf[j]);
        }
        if (c + 3 < NC) load_stage(c + 3);
    }
}

#define QK_STAGE 20480u
#define QK_SMEM  (4 * 20480)
#define AV_SMEM  (4 * 12288)
#define STG_ROW  264           // halves per staged epilogue row (padding)

// ---------------------------------------------------------------------------
// K1: fp16 logits = mask ? (q/T)@k^T : -60000.
// Block 64(n) x 256(m), 8 warps (2x4), warp 32x64, 4-stage ring.
// Smem-staged, fully-coalesced masked epilogue. Mask read with .cs.
// ---------------------------------------------------------------------------
__global__ void __launch_bounds__(256, 2) qk_mma_kernel(
    const int* __restrict__ mask)
{
    extern __shared__ char smem[];
    const uint32_t sb = smem_u32(smem);
    const int tid = threadIdx.x, warp = tid >> 5, lane = tid & 31;
    const int b = blockIdx.z, m0 = blockIdx.x * 256, n0 = blockIdx.y * 64;
    const int wrow = warp >> 2, wcol = warp & 3;

    const __half* srcA = g_q16 + ((size_t)b * N_ + n0) * D_;
    const __half* srcB = g_k16 + ((size_t)b * M_ + m0) * D_;

    float acc[2][8][4];
#pragma unroll
    for (int i = 0; i < 2; i++)
#pragma unroll
        for (int j = 0; j < 8; j++)
#pragma unroll
            for (int r = 0; r < 4; r++) acc[i][j][r] = 0.f;

    auto load_stage = [&](int c) {
        const uint32_t stg = sb + (uint32_t)(c & 3) * QK_STAGE;
        const int kt = c * 32;
#pragma unroll
        for (int u0 = 0; u0 < 1280; u0 += 256) {
            const int u = u0 + tid;
            const int rt = u >> 2, seg = u & 3;
            const __half* src;
            uint32_t base;
            int r;
            if (rt < 64) { src = srcA; base = 0u; r = rt; }
            else         { src = srcB; base = 4096u; r = rt - 64; }
            cp16(stg + base + sw64((uint32_t)(r * 64 + seg * 16)),
                 src + (size_t)r * D_ + kt + seg * 8);
        }
        CP_COMMIT();
    };

    const int NC = D_ / 32;                        // 8 chunks
    load_stage(0);
    load_stage(1);
    load_stage(2);

    for (int c = 0; c < NC; c++) {
        if (c + 3 <= NC) { CP_WAIT(2); }
        else if (c + 2 == NC) { CP_WAIT(1); }
        else { CP_WAIT(0); }
        __syncthreads();

        const uint32_t stg = sb + (uint32_t)(c & 3) * QK_STAGE;
#pragma unroll
        for (int kk = 0; kk < 2; kk++) {
            uint32_t af[2][4], bf[8][2];
#pragma unroll
            for (int i = 0; i < 2; i++) {
                uint32_t off = (uint32_t)((wrow * 32 + i * 16 + (lane & 15)) * 64
                                          + ((lane >> 4) * 16) + kk * 32);
                LDSM_X4(af[i][0], af[i][1], af[i][2], af[i][3], stg + sw64(off));
            }
#pragma unroll
            for (int jj = 0; jj < 4; jj++) {
                uint32_t off = (uint32_t)((wcol * 64 + jj * 16 + (lane & 15)) * 64
                                          + ((lane >> 4) * 16) + kk * 32);
                uint32_t r0, r1, r2, r3;
                LDSM_X4(r0, r1, r2, r3, stg + 4096u + sw64(off));
                bf[jj * 2][0] = r0; bf[jj * 2][1] = r2;
                bf[jj * 2 + 1][0] = r1; bf[jj * 2 + 1][1] = r3;
            }
#pragma unroll
            for (int i = 0; i < 2; i++)
#pragma unroll
                for (int j = 0; j < 8; j++)
                    MMA16816(acc[i][j], af[i], bf[j]);
        }
        if (c + 3 < NC) load_stage(c + 3);
    }

    // ---- Stage tile to smem (reuse pipeline ring; it is idle now). ----
    __half* hsm = (__half*)smem;
    const int r_lane = lane >> 2, c2 = lane & 3;   // half2 column index
#pragma unroll
    for (int i = 0; i < 2; i++) {
#pragma unroll
        for (int j = 0; j < 8; j++) {
            const int row0 = wrow * 32 + i * 16 + r_lane;
            const int col2 = wcol * 32 + j * 4 + c2;    // in half2 units
            ((__half2*)hsm)[row0 * (STG_ROW / 2) + col2] =
                __half2(__float2half(acc[i][j][0]), __float2half(acc[i][j][1]));
            ((__half2*)hsm)[(row0 + 8) * (STG_ROW / 2) + col2] =
                __half2(__float2half(acc[i][j][2]), __float2half(acc[i][j][3]));
        }
    }
    __syncthreads();

    // ---- Coalesced masked copy out: 64 rows x 32 uint4. ----
#pragma unroll
    for (int t0 = 0; t0 < 2048; t0 += 256) {
        const int t = t0 + tid;
        const int r = t >> 5, c16 = t & 31;
        uint4 raw = *(const uint4*)(hsm + r * STG_ROW + c16 * 8);
        const size_t gidx = ((size_t)b * N_ + n0 + r) * M_ + m0 + c16 * 8;
        int4 mk0 = __ldcs((const int4*)(mask + gidx));
        int4 mk1 = __ldcs((const int4*)(mask + gidx + 4));
        __half2* hp = (__half2*)&raw;
        const __half fill = __float2half(MASK_FILL_H);
        hp[0].x = mk0.x ? hp[0].x : fill;  hp[0].y = mk0.y ? hp[0].y : fill;
        hp[1].x = mk0.z ? hp[1].x : fill;  hp[1].y = mk0.w ? hp[1].y : fill;
        hp[2].x = mk1.x ? hp[2].x : fill;  hp[2].y = mk1.y ? hp[2].y : fill;
        hp[3].x = mk1.z ? hp[3].x : fill;  hp[3].y = mk1.w ? hp[3].y : fill;
        *(uint4*)(g_a16 + gidx) = raw;
    }
}

// ---------------------------------------------------------------------------
// K3: out = attn @ v.  Block 64(n) x 128(dv), 3 CTAs/SM. Output stores .cs.
// ---------------------------------------------------------------------------
__global__ void __launch_bounds__(256, 3) av_mma_kernel(float* __restrict__ out)
{
    extern __shared__ char smem[];
    const uint32_t sb = smem_u32(smem);
    const int tid = threadIdx.x, warp = tid >> 5, lane = tid & 31;
    const int b = blockIdx.z, c0 = blockIdx.x * 128, n0 = blockIdx.y * 64;
    const int wrow = warp >> 2, wcol = warp & 3;

    const __half* srcs[2] = {
        g_a16  + ((size_t)b * N_  + n0) * M_,
        g_vt16 + ((size_t)b * DV_ + c0) * M_ };

    float acc[2][4][4];
#pragma unroll
    for (int i = 0; i < 2; i++)
#pragma unroll
        for (int j = 0; j < 4; j++)
#pragma unroll
            for (int r = 0; r < 4; r++) acc[i][j][r] = 0.f;

    gemm_mainloop<M_ / 32>(srcs, M_, sb, tid, wrow, wcol, lane, acc);

    const int r_lane = lane >> 2, c_lane = (lane & 3) * 2;
#pragma unroll
    for (int i = 0; i < 2; i++) {
#pragma unroll
        for (int j = 0; j < 4; j++) {
            const int row0 = n0 + wrow * 32 + i * 16 + r_lane;
            const int col  = c0 + wcol * 32 + j * 8 + c_lane;
            const size_t idx0 = ((size_t)b * N_ + row0) * DV_ + col;
            const size_t idx1 = idx0 + (size_t)8 * DV_;
            __stcs((float2*)(out + idx0), make_float2(acc[i][j][0], acc[i][j][1]));
            __stcs((float2*)(out + idx1), make_float2(acc[i][j][2], acc[i][j][3]));
        }
    }
}

// ---------------------------------------------------------------------------
// K2: attn = softmax(fp16 logits) + softmax(oa).
// Single-touch traffic uses .cs: oa loads, fp32 attn stores. The fp16 attn
// write to g_a16 stays default-policy (re-read by av).
// ---------------------------------------------------------------------------
__global__ void __launch_bounds__(256) softmax_add_kernel(
    const float* __restrict__ oa, float* __restrict__ attn)
{
    const size_t row = blockIdx.x;
    const __half* lg = g_a16 + row * M_;
    float*        s  = attn  + row * M_;
    const float*  o  = oa    + row * M_;

    const int tid  = threadIdx.x;
    const int lane = tid & 31;
    const int warp = tid >> 5;
    const int base = tid * 8;

    float sv[8], ov[8];
    {
        uint4 raw = __ldcs((const uint4*)(lg + base));   // 8 halves, read-once
        const __half2* hp = (const __half2*)&raw;
#pragma unroll
        for (int i = 0; i < 4; i++) {
            float2 f = __half22float2(hp[i]);
            sv[i * 2] = f.x; sv[i * 2 + 1] = f.y;
        }
    }
    float4 o0 = __ldcs((const float4*)(o + base));
    float4 o1 = __ldcs((const float4*)(o + base) + 1);
    ov[0]=o0.x; ov[1]=o0.y; ov[2]=o0.z; ov[3]=o0.w;
    ov[4]=o1.x; ov[5]=o1.y; ov[6]=o1.z; ov[7]=o1.w;

    float smax = -3.4e38f, omax = -3.4e38f;
#pragma unroll
    for (int i = 0; i < 8; i++) { smax = fmaxf(smax, sv[i]); omax = fmaxf(omax, ov[i]); }
#pragma unroll
    for (int off = 16; off > 0; off >>= 1) {
        smax = fmaxf(smax, __shfl_xor_sync(0xffffffffu, smax, off));
        omax = fmaxf(omax, __shfl_xor_sync(0xffffffffu, omax, off));
    }
    __shared__ float red[4][8];
    if (lane == 0) { red[0][warp] = smax; red[1][warp] = omax; }
    __syncthreads();
#pragma unroll
    for (int w = 0; w < 8; w++) { smax = fmaxf(smax, red[0][w]); omax = fmaxf(omax, red[1][w]); }

    float ssum = 0.f, osum = 0.f;
#pragma unroll
    for (int i = 0; i < 8; i++) {
        sv[i] = __expf(sv[i] - smax);
        ov[i] = __expf(ov[i] - omax);
        ssum += sv[i]; osum += ov[i];
    }
#pragma unroll
    for (int off = 16; off > 0; off >>= 1) {
        ssum += __shfl_xor_sync(0xffffffffu, ssum, off);
        osum += __shfl_xor_sync(0xffffffffu, osum, off);
    }
    if (lane == 0) { red[2][warp] = ssum; red[3][warp] = osum; }
    __syncthreads();
    ssum = 0.f; osum = 0.f;
#pragma unroll
    for (int w = 0; w < 8; w++) { ssum += red[2][w]; osum += red[3][w]; }
    const float sinv = 1.0f / ssum;
    const float oinv = 1.0f / osum;

    float vals[8];
#pragma unroll
    for (int i = 0; i < 8; i++)
        vals[i] = sv[i] * sinv + ov[i] * oinv;
    __stcs((float4*)(s + base),
           make_float4(vals[0], vals[1], vals[2], vals[3]));
    __stcs((float4*)(s + base) + 1,
           make_float4(vals[4], vals[5], vals[6], vals[7]));
    uint4 raw;
    __half2* hp = (__half2*)&raw;
    hp[0] = {__float2half(vals[0]), __float2half(vals[1])};
    hp[1] = {__float2half(vals[2]), __float2half(vals[3])};
    hp[2] = {__float2half(vals[4]), __float2half(vals[5])};
    hp[3] = {__float2half(vals[6]), __float2half(vals[7])};
    *(uint4*)(g_a16 + row * M_ + base) = raw;
}

// ---------------------------------------------------------------------------
extern "C" void kernel_launch(void* const* d_in, const int* in_sizes, int n_in,
                              void* d_out, int out_size)
{
    const float* q    = (const float*)d_in[0];
    const float* k    = (const float*)d_in[1];
    const float* v    = (const float*)d_in[2];
    const float* oa   = (const float*)d_in[3];
    const int*   mask = (const int*)d_in[4];
    // d_in[5] = feature; always truthy for these shapes, ignored.

    float* out  = (float*)d_out;                        // [B, N, DV]
    float* attn = out + (size_t)B_ * N_ * DV_;          // [B, N, M]

    cudaFuncSetAttribute(qk_mma_kernel, cudaFuncAttributeMaxDynamicSharedMemorySize, QK_SMEM);
    cudaFuncSetAttribute(av_mma_kernel, cudaFuncAttributeMaxDynamicSharedMemorySize, AV_SMEM);

    const size_t qk_elems = QELEMS + (size_t)B_ * M_ * D_;
    prep_qk_kernel<<<qk_elems / 4 / 256, 256>>>(q, k);
    prep_vt_kernel<<<dim3(M_ / 32, DV_ / 32, B_), dim3(32, 8)>>>(v);

    qk_mma_kernel<<<dim3(M_ / 256, N_ / 64, B_), 256, QK_SMEM>>>(mask);
    softmax_add_kernel<<<B_ * N_, 256>>>(oa, attn);
    av_mma_kernel<<<dim3(DV_ / 128, N_ / 64, B_), 256, AV_SMEM>>>(out);
}

// round 17
// speedup vs baseline: 1.0987x; 1.0987x over previous
#include <cuda_runtime.h>
#include <cuda_fp16.h>
#include <cstdint>

#define B_  8
#define N_  4096
#define M_  2048
#define D_  256
#define DV_ 256
#define INV_T (1.0f / 16.0f)
#define MASK_FILL_H (-60000.0f)   // fp16-representable; exp-equivalent to -1e9

// ---------------------------------------------------------------------------
// Scratch (__device__ globals; no dynamic allocation allowed).
// g_a16 is dual-use: qk writes fp16 masked logits; softmax overwrites with
// fp16 attention weights (read by av).
// ---------------------------------------------------------------------------
__device__ __half g_q16[(size_t)B_ * N_ * D_];
__device__ __half g_k16[(size_t)B_ * M_ * D_];
__device__ __half g_vt16[(size_t)B_ * DV_ * M_];   // V^T [B, DV, M]
__device__ __half g_a16[(size_t)B_ * N_ * M_];     // logits -> attn (fp16)

// ---------------------------------------------------------------------------
// Helpers (plain sm_80+ PTX only — tcgen05 is feature-gated off this target).
// ---------------------------------------------------------------------------
__device__ __forceinline__ uint32_t smem_u32(const void* p) {
    uint32_t a;
    asm("{ .reg .u64 t; cvta.to.shared.u64 t, %1; cvt.u32.u64 %0, t; }"
        : "=r"(a) : "l"(p));
    return a;
}

__device__ __forceinline__ void cp16(uint32_t dst, const void* src) {
    asm volatile("cp.async.cg.shared.global [%0], [%1], 16;"
                 :: "r"(dst), "l"(src));
}
#define CP_COMMIT() asm volatile("cp.async.commit_group;" ::: "memory")
#define CP_WAIT(n)  asm volatile("cp.async.wait_group %0;" :: "n"(n) : "memory")

#define LDSM_X4(r0, r1, r2, r3, addr)                                         \
    asm volatile("ldmatrix.sync.aligned.m8n8.x4.shared.b16 {%0,%1,%2,%3}, [%4];" \
                 : "=r"(r0), "=r"(r1), "=r"(r2), "=r"(r3) : "r"(addr))

#define MMA16816(d, a, b)                                                     \
    asm volatile("mma.sync.aligned.m16n8k16.row.col.f32.f16.f16.f32 "         \
                 "{%0,%1,%2,%3}, {%4,%5,%6,%7}, {%8,%9}, {%0,%1,%2,%3};"      \
                 : "+f"((d)[0]), "+f"((d)[1]), "+f"((d)[2]), "+f"((d)[3])     \
                 : "r"((a)[0]), "r"((a)[1]), "r"((a)[2]), "r"((a)[3]),        \
                   "r"((b)[0]), "r"((b)[1]))

// SW64 swizzle for 64-byte rows (32 fp16): conflict-free ldmatrix phases.
__device__ __forceinline__ uint32_t sw64(uint32_t off) {
    return off ^ ((off >> 3) & 0x30);
}

// ---------------------------------------------------------------------------
// Prep kernels. prep_qk converts q (scaled) and k in one launch.
// ---------------------------------------------------------------------------
#define QELEMS ((size_t)B_ * N_ * D_)

__global__ void __launch_bounds__(256) prep_qk_kernel(
    const float* __restrict__ q, const float* __restrict__ k)
{
    size_t i = ((size_t)blockIdx.x * 256 + threadIdx.x) * 4;
    if (i < QELEMS) {
        float4 x = *(const float4*)(q + i);
        __half2* d = (__half2*)(g_q16 + i);
        d[0] = {__float2half(x.x * INV_T), __float2half(x.y * INV_T)};
        d[1] = {__float2half(x.z * INV_T), __float2half(x.w * INV_T)};
    } else {
        size_t j = i - QELEMS;
        float4 x = *(const float4*)(k + j);
        __half2* d = (__half2*)(g_k16 + j);
        d[0] = {__float2half(x.x), __float2half(x.y)};
        d[1] = {__float2half(x.z), __float2half(x.w)};
    }
}

__global__ void prep_vt_kernel(const float* __restrict__ v) {
    __shared__ float t[32][33];
    const int b = blockIdx.z, m0 = blockIdx.x * 32, c0 = blockIdx.y * 32;
    for (int j = threadIdx.y; j < 32; j += 8)
        t[j][threadIdx.x] = v[((size_t)b * M_ + m0 + j) * DV_ + c0 + threadIdx.x];
    __syncthreads();
    for (int j = threadIdx.y; j < 32; j += 8) {
        size_t o = ((size_t)b * DV_ + c0 + j) * M_ + m0 + threadIdx.x;
        g_vt16[o] = __float2half(t[threadIdx.x][j]);
    }
}

// ---------------------------------------------------------------------------
// AV mainloop (R11-proven): block 64x128, 8 warps 2x4, warp 32x32,
// K-chunks of 32, 4-stage ring. Stage = A 4KB | B 8KB = 12KB.
// ---------------------------------------------------------------------------
template <int NC>
__device__ __forceinline__ void gemm_mainloop(
    const __half* const* srcs, const size_t sstride,
    uint32_t sb, int tid, int wrow, int wcol, int lane, float acc[2][4][4])
{
    const uint32_t STAGE = 12288u;
    const uint32_t BBASE = 4096u;

    auto load_stage = [&](int c) {
        const uint32_t stg = sb + (uint32_t)(c & 3) * STAGE;
        const int kt = c * 32;
#pragma unroll
        for (int u0 = 0; u0 < 768; u0 += 256) {
            const int u = u0 + tid;
            const int rt = u >> 2, seg = u & 3;
            const __half* src;
            uint32_t base;
            int r;
            if (rt < 64) { src = srcs[0]; base = 0u; r = rt; }
            else         { src = srcs[1]; base = BBASE; r = rt - 64; }
            cp16(stg + base + sw64((uint32_t)(r * 64 + seg * 16)),
                 src + (size_t)r * sstride + kt + seg * 8);
        }
        CP_COMMIT();
    };

    load_stage(0);
    if (NC > 1) load_stage(1);
    if (NC > 2) load_stage(2);

    for (int c = 0; c < NC; c++) {
        if (c + 3 <= NC) { CP_WAIT(2); }
        else if (c + 2 == NC) { CP_WAIT(1); }
        else { CP_WAIT(0); }
        __syncthreads();

        const uint32_t stg = sb + (uint32_t)(c & 3) * STAGE;
#pragma unroll
        for (int kk = 0; kk < 2; kk++) {
            uint32_t af[2][4], bf[4][2];
#pragma unroll
            for (int i = 0; i < 2; i++) {
                uint32_t off = (uint32_t)((wrow * 32 + i * 16 + (lane & 15)) * 64
                                          + ((lane >> 4) * 16) + kk * 32);
                LDSM_X4(af[i][0], af[i][1], af[i][2], af[i][3], stg + sw64(off));
            }
#pragma unroll
            for (int jj = 0; jj < 2; jj++) {
                uint32_t off = (uint32_t)((wcol * 32 + jj * 16 + (lane & 15)) * 64
                                          + ((lane >> 4) * 16) + kk * 32);
                uint32_t r0, r1, r2, r3;
                LDSM_X4(r0, r1, r2, r3, stg + BBASE + sw64(off));
                bf[jj * 2][0] = r0; bf[jj * 2][1] = r2;
                bf[jj * 2 + 1][0] = r1; bf[jj * 2 + 1][1] = r3;
            }
#pragma unroll
            for (int i = 0; i < 2; i++)
#pragma unroll
                for (int j = 0; j < 4; j++)
                    MMA16816(acc[i][j], af[i], bf[j]);
        }
        if (c + 3 < NC) load_stage(c + 3);
    }
}

#define QK_STAGE 20480u
#define QK_SMEM  (4 * 20480)
#define AV_SMEM  (4 * 12288)
#define STG_ROW  264           // halves per staged epilogue row (padding)

// ---------------------------------------------------------------------------
// K1: fp16 logits = mask ? (q/T)@k^T : -60000.
// Block 64(n) x 256(m), 8 warps (2x4), warp 32x64, 4-stage ring.
// Smem-staged, fully-coalesced masked epilogue (R12/R15-proven).
// ---------------------------------------------------------------------------
__global__ void __launch_bounds__(256, 2) qk_mma_kernel(
    const int* __restrict__ mask)
{
    extern __shared__ char smem[];
    const uint32_t sb = smem_u32(smem);
    const int tid = threadIdx.x, warp = tid >> 5, lane = tid & 31;
    const int b = blockIdx.z, m0 = blockIdx.x * 256, n0 = blockIdx.y * 64;
    const int wrow = warp >> 2, wcol = warp & 3;

    const __half* srcA = g_q16 + ((size_t)b * N_ + n0) * D_;
    const __half* srcB = g_k16 + ((size_t)b * M_ + m0) * D_;

    float acc[2][8][4];
#pragma unroll
    for (int i = 0; i < 2; i++)
#pragma unroll
        for (int j = 0; j < 8; j++)
#pragma unroll
            for (int r = 0; r < 4; r++) acc[i][j][r] = 0.f;

    auto load_stage = [&](int c) {
        const uint32_t stg = sb + (uint32_t)(c & 3) * QK_STAGE;
        const int kt = c * 32;
#pragma unroll
        for (int u0 = 0; u0 < 1280; u0 += 256) {
            const int u = u0 + tid;
            const int rt = u >> 2, seg = u & 3;
            const __half* src;
            uint32_t base;
            int r;
            if (rt < 64) { src = srcA; base = 0u; r = rt; }
            else         { src = srcB; base = 4096u; r = rt - 64; }
            cp16(stg + base + sw64((uint32_t)(r * 64 + seg * 16)),
                 src + (size_t)r * D_ + kt + seg * 8);
        }
        CP_COMMIT();
    };

    const int NC = D_ / 32;                        // 8 chunks
    load_stage(0);
    load_stage(1);
    load_stage(2);

    for (int c = 0; c < NC; c++) {
        if (c + 3 <= NC) { CP_WAIT(2); }
        else if (c + 2 == NC) { CP_WAIT(1); }
        else { CP_WAIT(0); }
        __syncthreads();

        const uint32_t stg = sb + (uint32_t)(c & 3) * QK_STAGE;
#pragma unroll
        for (int kk = 0; kk < 2; kk++) {
            uint32_t af[2][4], bf[8][2];
#pragma unroll
            for (int i = 0; i < 2; i++) {
                uint32_t off = (uint32_t)((wrow * 32 + i * 16 + (lane & 15)) * 64
                                          + ((lane >> 4) * 16) + kk * 32);
                LDSM_X4(af[i][0], af[i][1], af[i][2], af[i][3], stg + sw64(off));
            }
#pragma unroll
            for (int jj = 0; jj < 4; jj++) {
                uint32_t off = (uint32_t)((wcol * 64 + jj * 16 + (lane & 15)) * 64
                                          + ((lane >> 4) * 16) + kk * 32);
                uint32_t r0, r1, r2, r3;
                LDSM_X4(r0, r1, r2, r3, stg + 4096u + sw64(off));
                bf[jj * 2][0] = r0; bf[jj * 2][1] = r2;
                bf[jj * 2 + 1][0] = r1; bf[jj * 2 + 1][1] = r3;
            }
#pragma unroll
            for (int i = 0; i < 2; i++)
#pragma unroll
                for (int j = 0; j < 8; j++)
                    MMA16816(acc[i][j], af[i], bf[j]);
        }
        if (c + 3 < NC) load_stage(c + 3);
    }

    // ---- Stage tile to smem (reuse pipeline ring; it is idle now). ----
    __half* hsm = (__half*)smem;
    const int r_lane = lane >> 2, c2 = lane & 3;   // half2 column index
#pragma unroll
    for (int i = 0; i < 2; i++) {
#pragma unroll
        for (int j = 0; j < 8; j++) {
            const int row0 = wrow * 32 + i * 16 + r_lane;
            const int col2 = wcol * 32 + j * 4 + c2;    // in half2 units
            ((__half2*)hsm)[row0 * (STG_ROW / 2) + col2] =
                __half2(__float2half(acc[i][j][0]), __float2half(acc[i][j][1]));
            ((__half2*)hsm)[(row0 + 8) * (STG_ROW / 2) + col2] =
                __half2(__float2half(acc[i][j][2]), __float2half(acc[i][j][3]));
        }
    }
    __syncthreads();

    // ---- Coalesced masked copy out: 64 rows x 32 uint4. ----
#pragma unroll
    for (int t0 = 0; t0 < 2048; t0 += 256) {
        const int t = t0 + tid;
        const int r = t >> 5, c16 = t & 31;
        uint4 raw = *(const uint4*)(hsm + r * STG_ROW + c16 * 8);
        const size_t gidx = ((size_t)b * N_ + n0 + r) * M_ + m0 + c16 * 8;
        int4 mk0 = *(const int4*)(mask + gidx);
        int4 mk1 = *(const int4*)(mask + gidx + 4);
        __half2* hp = (__half2*)&raw;
        const __half fill = __float2half(MASK_FILL_H);
        hp[0].x = mk0.x ? hp[0].x : fill;  hp[0].y = mk0.y ? hp[0].y : fill;
        hp[1].x = mk0.z ? hp[1].x : fill;  hp[1].y = mk0.w ? hp[1].y : fill;
        hp[2].x = mk1.x ? hp[2].x : fill;  hp[2].y = mk1.y ? hp[2].y : fill;
        hp[3].x = mk1.z ? hp[3].x : fill;  hp[3].y = mk1.w ? hp[3].y : fill;
        *(uint4*)(g_a16 + gidx) = raw;
    }
}

// ---------------------------------------------------------------------------
// K3: out = attn @ v.  Block 64(n) x 128(dv), 3 CTAs/SM (R11/R15-proven).
// ---------------------------------------------------------------------------
__global__ void __launch_bounds__(256, 3) av_mma_kernel(float* __restrict__ out)
{
    extern __shared__ char smem[];
    const uint32_t sb = smem_u32(smem);
    const int tid = threadIdx.x, warp = tid >> 5, lane = tid & 31;
    const int b = blockIdx.z, c0 = blockIdx.x * 128, n0 = blockIdx.y * 64;
    const int wrow = warp >> 2, wcol = warp & 3;

    const __half* srcs[2] = {
        g_a16  + ((size_t)b * N_  + n0) * M_,
        g_vt16 + ((size_t)b * DV_ + c0) * M_ };

    float acc[2][4][4];
#pragma unroll
    for (int i = 0; i < 2; i++)
#pragma unroll
        for (int j = 0; j < 4; j++)
#pragma unroll
            for (int r = 0; r < 4; r++) acc[i][j][r] = 0.f;

    gemm_mainloop<M_ / 32>(srcs, M_, sb, tid, wrow, wcol, lane, acc);

    const int r_lane = lane >> 2, c_lane = (lane & 3) * 2;
#pragma unroll
    for (int i = 0; i < 2; i++) {
#pragma unroll
        for (int j = 0; j < 4; j++) {
            const int row0 = n0 + wrow * 32 + i * 16 + r_lane;
            const int col  = c0 + wcol * 32 + j * 8 + c_lane;
            const size_t idx0 = ((size_t)b * N_ + row0) * DV_ + col;
            const size_t idx1 = idx0 + (size_t)8 * DV_;
            *(float2*)(out + idx0) = make_float2(acc[i][j][0], acc[i][j][1]);
            *(float2*)(out + idx1) = make_float2(acc[i][j][2], acc[i][j][3]);
        }
    }
}

// ---------------------------------------------------------------------------
// K2: attn = softmax(fp16 logits) + softmax(oa).
// 128 threads x 16 elems/thread per row: doubled per-thread MLP, 4-warp
// reductions (halved barrier cost). Writes fp32 attn + fp16 attn (in place).
// ---------------------------------------------------------------------------
__global__ void __launch_bounds__(128) softmax_add_kernel(
    const float* __restrict__ oa, float* __restrict__ attn)
{
    const size_t row = blockIdx.x;
    const __half* lg = g_a16 + row * M_;
    float*        s  = attn  + row * M_;
    const float*  o  = oa    + row * M_;

    const int tid  = threadIdx.x;
    const int lane = tid & 31;
    const int warp = tid >> 5;
    const int base = tid * 16;

    float sv[16], ov[16];
    {
        uint4 raw0 = *(const uint4*)(lg + base);        // halves 0..7
        uint4 raw1 = *(const uint4*)(lg + base + 8);    // halves 8..15
        const __half2* hp0 = (const __half2*)&raw0;
        const __half2* hp1 = (const __half2*)&raw1;
#pragma unroll
        for (int i = 0; i < 4; i++) {
            float2 f0 = __half22float2(hp0[i]);
            float2 f1 = __half22float2(hp1[i]);
            sv[i * 2]     = f0.x; sv[i * 2 + 1]     = f0.y;
            sv[8 + i * 2] = f1.x; sv[8 + i * 2 + 1] = f1.y;
        }
    }
    {
        const float4* op = (const float4*)(o + base);
#pragma unroll
        for (int i = 0; i < 4; i++) {
            float4 x = op[i];
            ov[i * 4] = x.x; ov[i * 4 + 1] = x.y;
            ov[i * 4 + 2] = x.z; ov[i * 4 + 3] = x.w;
        }
    }

    float smax = -3.4e38f, omax = -3.4e38f;
#pragma unroll
    for (int i = 0; i < 16; i++) { smax = fmaxf(smax, sv[i]); omax = fmaxf(omax, ov[i]); }
#pragma unroll
    for (int off = 16; off > 0; off >>= 1) {
        smax = fmaxf(smax, __shfl_xor_sync(0xffffffffu, smax, off));
        omax = fmaxf(omax, __shfl_xor_sync(0xffffffffu, omax, off));
    }
    __shared__ float red[4][4];
    if (lane == 0) { red[0][warp] = smax; red[1][warp] = omax; }
    __syncthreads();
#pragma unroll
    for (int w = 0; w < 4; w++) { smax = fmaxf(smax, red[0][w]); omax = fmaxf(omax, red[1][w]); }

    float ssum = 0.f, osum = 0.f;
#pragma unroll
    for (int i = 0; i < 16; i++) {
        sv[i] = __expf(sv[i] - smax);
        ov[i] = __expf(ov[i] - omax);
        ssum += sv[i]; osum += ov[i];
    }
#pragma unroll
    for (int off = 16; off > 0; off >>= 1) {
        ssum += __shfl_xor_sync(0xffffffffu, ssum, off);
        osum += __shfl_xor_sync(0xffffffffu, osum, off);
    }
    if (lane == 0) { red[2][warp] = ssum; red[3][warp] = osum; }
    __syncthreads();
    ssum = 0.f; osum = 0.f;
#pragma unroll
    for (int w = 0; w < 4; w++) { ssum += red[2][w]; osum += red[3][w]; }
    const float sinv = 1.0f / ssum;
    const float oinv = 1.0f / osum;

    float vals[16];
#pragma unroll
    for (int i = 0; i < 16; i++)
        vals[i] = sv[i] * sinv + ov[i] * oinv;

    float4* sp = (float4*)(s + base);
#pragma unroll
    for (int i = 0; i < 4; i++)
        sp[i] = make_float4(vals[i * 4], vals[i * 4 + 1],
                            vals[i * 4 + 2], vals[i * 4 + 3]);

    uint4 raw0, raw1;
    __half2* hp0 = (__half2*)&raw0;
    __half2* hp1 = (__half2*)&raw1;
#pragma unroll
    for (int i = 0; i < 4; i++) {
        hp0[i] = __half2(__float2half(vals[i * 2]),     __float2half(vals[i * 2 + 1]));
        hp1[i] = __half2(__float2half(vals[8 + i * 2]), __float2half(vals[8 + i * 2 + 1]));
    }
    *(uint4*)(g_a16 + row * M_ + base)     = raw0;
    *(uint4*)(g_a16 + row * M_ + base + 8) = raw1;
}

// ---------------------------------------------------------------------------
extern "C" void kernel_launch(void* const* d_in, const int* in_sizes, int n_in,
                              void* d_out, int out_size)
{
    const float* q    = (const float*)d_in[0];
    const float* k    = (const float*)d_in[1];
    const float* v    = (const float*)d_in[2];
    const float* oa   = (const float*)d_in[3];
    const int*   mask = (const int*)d_in[4];
    // d_in[5] = feature; always truthy for these shapes, ignored.

    float* out  = (float*)d_out;                        // [B, N, DV]
    float* attn = out + (size_t)B_ * N_ * DV_;          // [B, N, M]

    cudaFuncSetAttribute(qk_mma_kernel, cudaFuncAttributeMaxDynamicSharedMemorySize, QK_SMEM);
    cudaFuncSetAttribute(av_mma_kernel, cudaFuncAttributeMaxDynamicSharedMemorySize, AV_SMEM);

    const size_t qk_elems = QELEMS + (size_t)B_ * M_ * D_;
    prep_qk_kernel<<<qk_elems / 4 / 256, 256>>>(q, k);
    prep_vt_kernel<<<dim3(M_ / 32, DV_ / 32, B_), dim3(32, 8)>>>(v);

    qk_mma_kernel<<<dim3(M_ / 256, N_ / 64, B_), 256, QK_SMEM>>>(mask);
    softmax_add_kernel<<<B_ * N_, 128>>>(oa, attn);
    av_mma_kernel<<<dim3(DV_ / 128, N_ / 64, B_), 256, AV_SMEM>>>(out);
}